// round 2
// baseline (speedup 1.0000x reference)
#include <cuda_runtime.h>

// ImportancePooling: out[n, :] = sum_k wnorm[n,k] * x[neighbors[n,k], :]
// N=100000, K=32, D=64. One warp per node; lane handles 2 floats (float2).

constexpr int K = 32;
constexpr int D = 64;

__global__ __launch_bounds__(256)
void importance_pool_kernel(const float* __restrict__ x,
                            const int* __restrict__ neighbors,
                            const float* __restrict__ weights,
                            float* __restrict__ out,
                            int N) {
    const int warp = (blockIdx.x * blockDim.x + threadIdx.x) >> 5;
    const int lane = threadIdx.x & 31;
    if (warp >= N) return;

    // Lane k owns neighbor k's weight and index (K == 32 == warp size).
    const float w_raw = weights[(size_t)warp * K + lane];
    const int   idx   = neighbors[(size_t)warp * K + lane];

    // Warp-wide weight sum.
    float s = w_raw;
    #pragma unroll
    for (int o = 16; o > 0; o >>= 1)
        s += __shfl_xor_sync(0xffffffffu, s, o);

    const float wn = (s > 0.0f) ? (w_raw / s) : w_raw;

    // Each lane accumulates 2 features of the output row.
    float2 acc = make_float2(0.0f, 0.0f);

    #pragma unroll
    for (int j = 0; j < K; ++j) {
        const int   nj = __shfl_sync(0xffffffffu, idx, j);
        const float wj = __shfl_sync(0xffffffffu, wn,  j);
        const float2 v = *reinterpret_cast<const float2*>(
            x + (size_t)nj * D + lane * 2);
        acc.x = fmaf(wj, v.x, acc.x);
        acc.y = fmaf(wj, v.y, acc.y);
    }

    *reinterpret_cast<float2*>(out + (size_t)warp * D + lane * 2) = acc;
}

extern "C" void kernel_launch(void* const* d_in, const int* in_sizes, int n_in,
                              void* d_out, int out_size) {
    const float* x         = (const float*)d_in[0];
    const int*   neighbors = (const int*)d_in[1];
    const float* weights   = (const float*)d_in[2];
    float*       out       = (float*)d_out;

    const int N = in_sizes[1] / K;  // neighbors has N*K elements

    const int threads = 256;                 // 8 warps -> 8 nodes per block
    const int nodes_per_block = threads / 32;
    const int blocks = (N + nodes_per_block - 1) / nodes_per_block;
    importance_pool_kernel<<<blocks, threads>>>(x, neighbors, weights, out, N);
}

// round 3
// speedup vs baseline: 1.2197x; 1.2197x over previous
#include <cuda_runtime.h>

// ImportancePooling: out[n,:] = sum_k wnorm[n,k] * x[neighbors[n,k],:]
// N=100000, K=32, D=64.
// v2: 2 nodes per warp (16 lanes x float4 each), single packed 32-bit
// shfl per neighbor (idx<<15 | 15-bit fixed-point normalized weight)
// to cut SHFL traffic through the L1/MIO datapath 4x vs v1.

constexpr int K = 32;
constexpr int D = 64;   // 16 float4 per row

__global__ __launch_bounds__(256)
void importance_pool2_kernel(const float4* __restrict__ x4,
                             const int* __restrict__ neighbors,
                             const float* __restrict__ weights,
                             float4* __restrict__ out4,
                             int nWarpsWork) {
    const int warp = (blockIdx.x * blockDim.x + threadIdx.x) >> 5;
    const int lane = threadIdx.x & 31;
    if (warp >= nWarpsWork) return;           // whole warp exits together

    const int grp  = lane >> 4;               // 0 or 1: which node in this warp
    const int s    = lane & 15;               // sub-lane within the node group
    const int node = warp * 2 + grp;          // N is even; grid sized exactly

    const int base = node * K;

    // Each lane owns neighbors s and s+16 of its node.
    const float w0  = weights[base + s];
    const float w1  = weights[base + s + 16];
    const int   id0 = neighbors[base + s];
    const int   id1 = neighbors[base + s + 16];

    // Half-warp (16-lane) weight sum; xor offsets < 16 stay inside the group.
    float t = w0 + w1;
    #pragma unroll
    for (int o = 8; o > 0; o >>= 1)
        t += __shfl_xor_sync(0xffffffffu, t, o);

    const float inv = (t > 0.0f) ? (1.0f / t) : 1.0f;  // zero-sum: keep raw
    const float wn0 = w0 * inv;
    const float wn1 = w1 * inv;

    // Pack: idx in bits [15:32), weight as 15-bit fixed point in [0:15).
    const unsigned p0 = ((unsigned)id0 << 15) |
                        (unsigned)__float2int_rn(wn0 * 32767.0f);
    const unsigned p1 = ((unsigned)id1 << 15) |
                        (unsigned)__float2int_rn(wn1 * 32767.0f);

    float4 acc = make_float4(0.0f, 0.0f, 0.0f, 0.0f);

    #pragma unroll
    for (int j = 0; j < K; ++j) {
        // Source lane for this group's neighbor j; one SHFL serves both groups.
        const int src = (grp << 4) | (j & 15);
        const unsigned pj = __shfl_sync(0xffffffffu, (j < 16) ? p0 : p1, src);

        const float wj = (float)(pj & 0x7fffu) * (1.0f / 32767.0f);
        const unsigned nj = pj >> 15;

        const float4 v = __ldg(&x4[(size_t)nj * (D / 4) + s]);
        acc.x = fmaf(wj, v.x, acc.x);
        acc.y = fmaf(wj, v.y, acc.y);
        acc.z = fmaf(wj, v.z, acc.z);
        acc.w = fmaf(wj, v.w, acc.w);
    }

    out4[(size_t)node * (D / 4) + s] = acc;
}

extern "C" void kernel_launch(void* const* d_in, const int* in_sizes, int n_in,
                              void* d_out, int out_size) {
    const float4* x4        = (const float4*)d_in[0];
    const int*    neighbors = (const int*)d_in[1];
    const float*  weights   = (const float*)d_in[2];
    float4*       out4      = (float4*)d_out;

    const int N = in_sizes[1] / K;        // neighbors has N*K elements
    const int nWarpsWork = N / 2;         // 2 nodes per warp (N even)

    const int threads = 256;              // 8 warps/block -> 16 nodes/block
    const int warpsPerBlock = threads / 32;
    const int blocks = (nWarpsWork + warpsPerBlock - 1) / warpsPerBlock;
    importance_pool2_kernel<<<blocks, threads>>>(x4, neighbors, weights, out4,
                                                 nWarpsWork);
}

// round 5
// speedup vs baseline: 1.4923x; 1.2235x over previous
#include <cuda_runtime.h>
#include <cuda_fp16.h>

// ImportancePooling: out[n,:] = sum_k wnorm[n,k] * x[neighbors[n,k],:]
// N=100000, K=32, D=64.
// v4: fixes v3's convert-kernel grid (8 floats per thread, not 16 — v3
// left half of g_xh unwritten -> rel_err 1/sqrt(2)).
// Pass 1: fp32 -> fp16 convert into __device__ scratch (halves gather bytes).
// Pass 2: gather with 4 nodes per warp (8 lanes x 128B fp16 row via
// LDG.128), one packed (idx,weight) shfl per neighbor serving all 4 nodes.

constexpr int K = 32;
constexpr int D = 64;
constexpr int MAXN = 100000;

__device__ __half g_xh[(size_t)MAXN * D];

__global__ __launch_bounds__(256)
void convert_half_kernel(const float4* __restrict__ x4, int nVec8) {
    const int i = blockIdx.x * blockDim.x + threadIdx.x;
    if (i >= nVec8) return;                 // i indexes 8-float / 8-half chunks
    const float4 a = x4[2 * i];
    const float4 b = x4[2 * i + 1];
    __half2 h0 = __floats2half2_rn(a.x, a.y);
    __half2 h1 = __floats2half2_rn(a.z, a.w);
    __half2 h2 = __floats2half2_rn(b.x, b.y);
    __half2 h3 = __floats2half2_rn(b.z, b.w);
    uint4 o;
    o.x = *reinterpret_cast<unsigned*>(&h0);
    o.y = *reinterpret_cast<unsigned*>(&h1);
    o.z = *reinterpret_cast<unsigned*>(&h2);
    o.w = *reinterpret_cast<unsigned*>(&h3);
    reinterpret_cast<uint4*>(g_xh)[i] = o;  // 16 B = 8 halfs
}

__global__ __launch_bounds__(256)
void importance_pool4_kernel(const int* __restrict__ neighbors,
                             const float* __restrict__ weights,
                             float4* __restrict__ out4,
                             int nWarpsWork) {
    const int warp = (blockIdx.x * blockDim.x + threadIdx.x) >> 5;
    const int lane = threadIdx.x & 31;
    if (warp >= nWarpsWork) return;          // whole warp exits together

    const int grp  = lane >> 3;              // 0..3: node within this warp
    const int s    = lane & 7;               // sub-lane within node group
    const int node = warp * 4 + grp;         // N divisible by 4

    const int base = node * K + s;

    // Each lane owns neighbors s, s+8, s+16, s+24 of its node.
    const float w0 = weights[base];
    const float w1 = weights[base + 8];
    const float w2 = weights[base + 16];
    const float w3 = weights[base + 24];
    const int   i0 = neighbors[base];
    const int   i1 = neighbors[base + 8];
    const int   i2 = neighbors[base + 16];
    const int   i3 = neighbors[base + 24];

    // 8-lane group weight sum (xor offsets < 8 stay inside the group).
    float t = (w0 + w1) + (w2 + w3);
    #pragma unroll
    for (int o = 4; o > 0; o >>= 1)
        t += __shfl_xor_sync(0xffffffffu, t, o);

    const float inv = (t > 0.0f) ? (1.0f / t) : 1.0f;  // zero-sum: keep raw

    // Pack: idx in bits [15:32), normalized weight as 15-bit fixed point.
    const unsigned p0 = ((unsigned)i0 << 15) | (unsigned)__float2int_rn(w0 * inv * 32767.0f);
    const unsigned p1 = ((unsigned)i1 << 15) | (unsigned)__float2int_rn(w1 * inv * 32767.0f);
    const unsigned p2 = ((unsigned)i2 << 15) | (unsigned)__float2int_rn(w2 * inv * 32767.0f);
    const unsigned p3 = ((unsigned)i3 << 15) | (unsigned)__float2int_rn(w3 * inv * 32767.0f);

    float acc0 = 0.f, acc1 = 0.f, acc2 = 0.f, acc3 = 0.f;
    float acc4 = 0.f, acc5 = 0.f, acc6 = 0.f, acc7 = 0.f;

    const uint4* __restrict__ xh4 = reinterpret_cast<const uint4*>(g_xh);

    #pragma unroll
    for (int j = 0; j < K; ++j) {
        // Source lane for this group's neighbor j; one SHFL serves 4 nodes.
        const int src = (grp << 3) | (j & 7);
        const unsigned pv = (j < 8) ? p0 : (j < 16) ? p1 : (j < 24) ? p2 : p3;
        const unsigned pj = __shfl_sync(0xffffffffu, pv, src);

        const float    wj = (float)(pj & 0x7fffu) * (1.0f / 32767.0f);
        const unsigned nj = pj >> 15;

        // 16 B = 8 halfs of the neighbor's fp16 row (row = 128 B = 8 lanes).
        const uint4 v = __ldg(&xh4[(size_t)nj * 8 + s]);
        const float2 f0 = __half22float2(*reinterpret_cast<const __half2*>(&v.x));
        const float2 f1 = __half22float2(*reinterpret_cast<const __half2*>(&v.y));
        const float2 f2 = __half22float2(*reinterpret_cast<const __half2*>(&v.z));
        const float2 f3 = __half22float2(*reinterpret_cast<const __half2*>(&v.w));

        acc0 = fmaf(wj, f0.x, acc0);
        acc1 = fmaf(wj, f0.y, acc1);
        acc2 = fmaf(wj, f1.x, acc2);
        acc3 = fmaf(wj, f1.y, acc3);
        acc4 = fmaf(wj, f2.x, acc4);
        acc5 = fmaf(wj, f2.y, acc5);
        acc6 = fmaf(wj, f3.x, acc6);
        acc7 = fmaf(wj, f3.y, acc7);
    }

    // Output row = 256 B fp32; lane s owns floats [8s, 8s+8).
    const size_t ob = (size_t)node * (D / 4) + 2 * s;
    out4[ob]     = make_float4(acc0, acc1, acc2, acc3);
    out4[ob + 1] = make_float4(acc4, acc5, acc6, acc7);
}

extern "C" void kernel_launch(void* const* d_in, const int* in_sizes, int n_in,
                              void* d_out, int out_size) {
    const float4* x4        = (const float4*)d_in[0];
    const int*    neighbors = (const int*)d_in[1];
    const float*  weights   = (const float*)d_in[2];
    float4*       out4      = (float4*)d_out;

    const int N = in_sizes[1] / K;            // neighbors has N*K elements

    // Pass 1: fp32 -> fp16 convert. Each thread handles 8 floats -> 8 halfs.
    const int nVec8 = (N * D) / 8;
    convert_half_kernel<<<(nVec8 + 255) / 256, 256>>>(x4, nVec8);

    // Pass 2: gather + pool, 4 nodes per warp.
    const int nWarpsWork = N / 4;
    const int threads = 256;
    const int blocks = (nWarpsWork + (threads / 32) - 1) / (threads / 32);
    importance_pool4_kernel<<<blocks, threads>>>(neighbors, weights, out4,
                                                 nWarpsWork);
}

// round 6
// speedup vs baseline: 1.5788x; 1.0580x over previous
#include <cuda_runtime.h>
#include <cuda_fp16.h>

// ImportancePooling: out[n,:] = sum_k wnorm[n,k] * x[neighbors[n,k],:]
// N=100000, K=32, D=64.
// v5: inner loop in fp16 — 4x HFMA2 replaces 8x F2F + 8x FFMA (R5 showed
// issue-bound at 63% with mem at 55%). Accumulation split into 4 chunks of
// 8 neighbors (fp16) combined in fp32 to bound rounding error. Weight is
// packed as raw fp16 bits (sign-free) in the low 15 bits of the shfl word;
// unpack = AND + PRMT broadcast.

constexpr int K = 32;
constexpr int D = 64;
constexpr int MAXN = 100000;

__device__ __half g_xh[(size_t)MAXN * D];

__global__ __launch_bounds__(256)
void convert_half_kernel(const float4* __restrict__ x4, int nVec8) {
    const int i = blockIdx.x * blockDim.x + threadIdx.x;
    if (i >= nVec8) return;                 // i indexes 8-float / 8-half chunks
    const float4 a = x4[2 * i];
    const float4 b = x4[2 * i + 1];
    __half2 h0 = __floats2half2_rn(a.x, a.y);
    __half2 h1 = __floats2half2_rn(a.z, a.w);
    __half2 h2 = __floats2half2_rn(b.x, b.y);
    __half2 h3 = __floats2half2_rn(b.z, b.w);
    uint4 o;
    o.x = *reinterpret_cast<unsigned*>(&h0);
    o.y = *reinterpret_cast<unsigned*>(&h1);
    o.z = *reinterpret_cast<unsigned*>(&h2);
    o.w = *reinterpret_cast<unsigned*>(&h3);
    reinterpret_cast<uint4*>(g_xh)[i] = o;  // 16 B = 8 halfs
}

__global__ __launch_bounds__(256)
void importance_pool5_kernel(const int* __restrict__ neighbors,
                             const float* __restrict__ weights,
                             float4* __restrict__ out4,
                             int nWarpsWork) {
    const int warp = (blockIdx.x * blockDim.x + threadIdx.x) >> 5;
    const int lane = threadIdx.x & 31;
    if (warp >= nWarpsWork) return;          // whole warp exits together

    const int grp  = lane >> 3;              // 0..3: node within this warp
    const int s    = lane & 7;               // sub-lane within node group
    const int node = warp * 4 + grp;         // N divisible by 4

    const int base = node * K + s;

    // Each lane owns neighbors s, s+8, s+16, s+24 of its node.
    const float w0 = weights[base];
    const float w1 = weights[base + 8];
    const float w2 = weights[base + 16];
    const float w3 = weights[base + 24];
    const int   i0 = neighbors[base];
    const int   i1 = neighbors[base + 8];
    const int   i2 = neighbors[base + 16];
    const int   i3 = neighbors[base + 24];

    // 8-lane group weight sum (xor offsets < 8 stay inside the group).
    float t = (w0 + w1) + (w2 + w3);
    #pragma unroll
    for (int o = 4; o > 0; o >>= 1)
        t += __shfl_xor_sync(0xffffffffu, t, o);

    const float inv = (t > 0.0f) ? (1.0f / t) : 1.0f;  // zero-sum: keep raw

    // Pack: idx in bits [15:32), normalized weight as raw fp16 bits
    // (weights >= 0 so the sign bit is 0 and 15 bits hold the full value).
    const unsigned p0 = ((unsigned)i0 << 15) |
                        (unsigned)__half_as_ushort(__float2half_rn(w0 * inv));
    const unsigned p1 = ((unsigned)i1 << 15) |
                        (unsigned)__half_as_ushort(__float2half_rn(w1 * inv));
    const unsigned p2 = ((unsigned)i2 << 15) |
                        (unsigned)__half_as_ushort(__float2half_rn(w2 * inv));
    const unsigned p3 = ((unsigned)i3 << 15) |
                        (unsigned)__half_as_ushort(__float2half_rn(w3 * inv));

    // 4 accumulation chunks (8 neighbors each) x 4 half2 feature slots.
    __half2 acc[4][4];
    #pragma unroll
    for (int c = 0; c < 4; ++c)
        #pragma unroll
        for (int q = 0; q < 4; ++q)
            acc[c][q] = __half2half2(__ushort_as_half(0));

    const uint4* __restrict__ xh4 = reinterpret_cast<const uint4*>(g_xh);

    #pragma unroll
    for (int j = 0; j < K; ++j) {
        const int c = j >> 3;                // compile-time chunk index
        // Source lane for this group's neighbor j; one SHFL serves 4 nodes.
        const int src = (grp << 3) | (j & 7);
        const unsigned pv = (j < 8) ? p0 : (j < 16) ? p1 : (j < 24) ? p2 : p3;
        const unsigned pj = __shfl_sync(0xffffffffu, pv, src);

        // Weight: low 15 bits are fp16 bits; broadcast to both halves (PRMT).
        unsigned wpk = __byte_perm(pj & 0x7fffu, 0u, 0x1010);
        const __half2 wh2 = *reinterpret_cast<__half2*>(&wpk);
        const unsigned nj = pj >> 15;

        // 16 B = 8 halfs of the neighbor's fp16 row (row = 128 B = 8 lanes).
        uint4 v = __ldg(&xh4[(size_t)nj * 8 + s]);
        acc[c][0] = __hfma2(wh2, *reinterpret_cast<__half2*>(&v.x), acc[c][0]);
        acc[c][1] = __hfma2(wh2, *reinterpret_cast<__half2*>(&v.y), acc[c][1]);
        acc[c][2] = __hfma2(wh2, *reinterpret_cast<__half2*>(&v.z), acc[c][2]);
        acc[c][3] = __hfma2(wh2, *reinterpret_cast<__half2*>(&v.w), acc[c][3]);
    }

    // Combine the 4 chunks in fp32.
    float2 r[4];
    #pragma unroll
    for (int q = 0; q < 4; ++q) {
        const float2 a0 = __half22float2(acc[0][q]);
        const float2 a1 = __half22float2(acc[1][q]);
        const float2 a2 = __half22float2(acc[2][q]);
        const float2 a3 = __half22float2(acc[3][q]);
        r[q] = make_float2((a0.x + a1.x) + (a2.x + a3.x),
                           (a0.y + a1.y) + (a2.y + a3.y));
    }

    // Output row = 256 B fp32; lane s owns floats [8s, 8s+8).
    const size_t ob = (size_t)node * (D / 4) + 2 * s;
    out4[ob]     = make_float4(r[0].x, r[0].y, r[1].x, r[1].y);
    out4[ob + 1] = make_float4(r[2].x, r[2].y, r[3].x, r[3].y);
}

extern "C" void kernel_launch(void* const* d_in, const int* in_sizes, int n_in,
                              void* d_out, int out_size) {
    const float4* x4        = (const float4*)d_in[0];
    const int*    neighbors = (const int*)d_in[1];
    const float*  weights   = (const float*)d_in[2];
    float4*       out4      = (float4*)d_out;

    const int N = in_sizes[1] / K;            // neighbors has N*K elements

    // Pass 1: fp32 -> fp16 convert. Each thread handles 8 floats -> 8 halfs.
    const int nVec8 = (N * D) / 8;
    convert_half_kernel<<<(nVec8 + 255) / 256, 256>>>(x4, nVec8);

    // Pass 2: gather + pool, 4 nodes per warp.
    const int nWarpsWork = N / 4;
    const int threads = 256;
    const int blocks = (nWarpsWork + (threads / 32) - 1) / (threads / 32);
    importance_pool5_kernel<<<blocks, threads>>>(neighbors, weights, out4,
                                                 nWarpsWork);
}